// round 6
// baseline (speedup 1.0000x reference)
#include <cuda_runtime.h>
#include <cuda_fp8.h>
#include <cuda_fp16.h>
#include <cstdint>

// ============================================================================
// out = dequant( fp8_quant(x) @ fp8_quant(weight^T)^T )
//   x: [8, 8192, 512] f32  -> M=65536, K=512;  weight: [512,512] -> [N,K] fp8
// Per-tensor dynamic scales: s = 448 / max(amax, 1e-12)
//
// Plain sm_103 target (no tcgen05). GEMM uses fp8 mma.sync m16n8k32 (sm_89+
// baseline ISA). fp8 tiles loaded K-contiguous; ldmatrix.b16 on fp8 data
// yields exactly the e4m3 fragment byte layout (4 consecutive k-bytes/lane).
// Resubmission: round-4 bench died to container infra (same as round 2).
// ============================================================================

static constexpr int KDIM = 512;
static constexpr int NDIM = 512;
static constexpr long long MDIM = 65536LL;

__device__ unsigned g_amax[2];            // bits of amax(x), amax(w)
__device__ uint8_t  g_xq[33554432];       // M*K e4m3 (32 MB)
__device__ uint8_t  g_wq[262144];         // N*K e4m3 (weight^T)

// ---------------------------------------------------------------------------
__device__ __forceinline__ uint32_t smem_u32(const void* p) {
    uint32_t a;
    asm("{ .reg .u64 t; cvta.to.shared.u64 t, %1; cvt.u32.u64 %0, t; }"
        : "=r"(a) : "l"(p));
    return a;
}

#define CP_ASYNC16(dst, src) \
    asm volatile("cp.async.cg.shared.global [%0], [%1], 16;" :: "r"(dst), "l"(src))
#define CP_COMMIT() asm volatile("cp.async.commit_group;" ::: "memory")
#define CP_WAIT(n)  asm volatile("cp.async.wait_group %0;" :: "n"(n) : "memory")

#define LDMATRIX_X4(r0, r1, r2, r3, addr) \
    asm volatile("ldmatrix.sync.aligned.m8n8.x4.shared.b16 {%0,%1,%2,%3}, [%4];" \
                 : "=r"(r0), "=r"(r1), "=r"(r2), "=r"(r3) : "r"(addr))

// fp8 e4m3 MMA, m16n8k32, f32 accumulate
#define MMA_FP8(d, a, b0, b1) \
    asm volatile("mma.sync.aligned.m16n8k32.row.col.f32.e4m3.e4m3.f32 " \
                 "{%0,%1,%2,%3}, {%4,%5,%6,%7}, {%8,%9}, {%0,%1,%2,%3};" \
                 : "+f"((d)[0]), "+f"((d)[1]), "+f"((d)[2]), "+f"((d)[3]) \
                 : "r"((a)[0]), "r"((a)[1]), "r"((a)[2]), "r"((a)[3]), \
                   "r"(b0), "r"(b1))

__device__ __forceinline__ uint32_t sw128(uint32_t off) {
    return off ^ ((off >> 3) & 0x70);
}

// ---------------------------------------------------------------------------
// Kernel 0: zero amax accumulators
// ---------------------------------------------------------------------------
__global__ void init_amax_kernel() {
    if (threadIdx.x < 2) g_amax[threadIdx.x] = 0u;
}

// ---------------------------------------------------------------------------
// Kernel 1: global amax (float4 grid-stride, atomicMax on positive-float bits)
// ---------------------------------------------------------------------------
__global__ void amax_kernel(const float4* __restrict__ p, int n4, int dst_idx) {
    float m = 0.0f;
    for (int i = blockIdx.x * blockDim.x + threadIdx.x; i < n4;
         i += gridDim.x * blockDim.x) {
        float4 v = p[i];
        m = fmaxf(m, fmaxf(fmaxf(fabsf(v.x), fabsf(v.y)),
                           fmaxf(fabsf(v.z), fabsf(v.w))));
    }
    #pragma unroll
    for (int o = 16; o > 0; o >>= 1) m = fmaxf(m, __shfl_xor_sync(0xFFFFFFFFu, m, o));
    __shared__ float sm[8];
    if ((threadIdx.x & 31) == 0) sm[threadIdx.x >> 5] = m;
    __syncthreads();
    if (threadIdx.x < 32) {
        float v = (threadIdx.x < (blockDim.x >> 5)) ? sm[threadIdx.x] : 0.0f;
        #pragma unroll
        for (int o = 4; o > 0; o >>= 1) v = fmaxf(v, __shfl_xor_sync(0xFFFFFFFFu, v, o));
        if (threadIdx.x == 0) atomicMax(&g_amax[dst_idx], __float_as_uint(v));
    }
}

// ---------------------------------------------------------------------------
// Kernel 2: quantize x: f32 -> e4m3 (RN satfinite, as reference), store fp8
// ---------------------------------------------------------------------------
__global__ void quant_x_kernel(const float4* __restrict__ x, int n4) {
    float scale = 448.0f / fmaxf(__uint_as_float(g_amax[0]), 1e-12f);
    uchar4* __restrict__ out = reinterpret_cast<uchar4*>(g_xq);
    for (int i = blockIdx.x * blockDim.x + threadIdx.x; i < n4;
         i += gridDim.x * blockDim.x) {
        float4 v = x[i];
        uchar4 q;
        q.x = __nv_cvt_float_to_fp8(v.x * scale, __NV_SATFINITE, __NV_E4M3);
        q.y = __nv_cvt_float_to_fp8(v.y * scale, __NV_SATFINITE, __NV_E4M3);
        q.z = __nv_cvt_float_to_fp8(v.z * scale, __NV_SATFINITE, __NV_E4M3);
        q.w = __nv_cvt_float_to_fp8(v.w * scale, __NV_SATFINITE, __NV_E4M3);
        out[i] = q;
    }
}

// ---------------------------------------------------------------------------
// Kernel 3: quantize weight [K,N] -> g_wq [N,K] (transposed) e4m3
// ---------------------------------------------------------------------------
__global__ void quant_w_kernel(const float* __restrict__ w) {
    int idx = blockIdx.x * blockDim.x + threadIdx.x;   // idx = k*512 + n
    if (idx >= KDIM * NDIM) return;
    float scale = 448.0f / fmaxf(__uint_as_float(g_amax[1]), 1e-12f);
    int k = idx >> 9;
    int n = idx & 511;
    g_wq[n * KDIM + k] =
        __nv_cvt_float_to_fp8(w[idx] * scale, __NV_SATFINITE, __NV_E4M3);
}

// ---------------------------------------------------------------------------
// Kernel 4: fp8 GEMM  out[M,N] = (xq @ wq^T) * inv_scale
// CTA tile 128x128, BK=128 fp8 (128 B SW128 rows), double-buffered cp.async,
// 8 warps 4x2, warp tile 32x64, mma m16n8k32 e4m3 with f32 accumulate.
// ---------------------------------------------------------------------------
static constexpr int BM = 128;
static constexpr int BN = 128;
static constexpr int BKB = 128;                    // fp8 per chunk (bytes)
static constexpr int ROWB = 128;                   // bytes per smem row
static constexpr int A_TILE = BM * ROWB;           // 16384 B
static constexpr int B_TILE = BN * ROWB;           // 16384 B
static constexpr int STAGE = A_TILE + B_TILE;      // 32768 B
static constexpr uint32_t SMEM_DYN = 2 * STAGE;    // 65536 B
static constexpr int NCHUNK = KDIM / BKB;          // 4

__device__ __forceinline__ void load_tile(uint32_t smem_dst,
                                          const uint8_t* __restrict__ gsrc,
                                          int k0, int tid) {
    // 128 rows x 128 B (fp8) at K offset k0; gmem row stride = 512 B.
    #pragma unroll
    for (int i = 0; i < 4; i++) {
        int l = tid + i * 256;               // 0..1023 chunk id
        int r = l >> 3;                      // row
        int c = (l & 7) * 16;                // byte offset within 128B chunk row
        uint32_t off = (uint32_t)(r * ROWB + c);
        CP_ASYNC16(smem_dst + sw128(off), gsrc + (size_t)r * KDIM + k0 + c);
    }
}

__global__ void __launch_bounds__(256) gemm_kernel(float* __restrict__ out) {
    extern __shared__ char smem[];
    uint32_t base = smem_u32(smem);
    int tid = threadIdx.x;
    int wid = tid >> 5;
    int lane = tid & 31;
    int wm = wid & 3;            // 4 warps along M (32 rows each)
    int wn = wid >> 2;           // 2 warps along N (64 cols each)
    int n_tile = blockIdx.x;     // 0..3
    int m_tile = blockIdx.y;     // 0..511

    const uint8_t* gA = g_xq + (size_t)m_tile * BM * KDIM;
    const uint8_t* gB = g_wq + (size_t)n_tile * BN * KDIM;

    float acc[2][8][4];
    #pragma unroll
    for (int mi = 0; mi < 2; mi++)
        #pragma unroll
        for (int j = 0; j < 8; j++)
            #pragma unroll
            for (int t = 0; t < 4; t++) acc[mi][j][t] = 0.0f;

    // Prologue: stage 0
    load_tile(base, gA, 0, tid);
    load_tile(base + A_TILE, gB, 0, tid);
    CP_COMMIT();

    // ldmatrix lane addressing: 16 rows x 32B per x4 (two 16B column halves)
    int lrow = lane & 15;
    int lcol = (lane >> 4) * 16;             // byte offset

    #pragma unroll 1
    for (int it = 0; it < NCHUNK; it++) {
        CP_WAIT(0);
        __syncthreads();

        if (it + 1 < NCHUNK) {
            uint32_t nb = base + ((it + 1) & 1) * STAGE;
            load_tile(nb, gA, (it + 1) * BKB, tid);
            load_tile(nb + A_TILE, gB, (it + 1) * BKB, tid);
            CP_COMMIT();
        }

        uint32_t sA = base + (it & 1) * STAGE;
        uint32_t sB = sA + A_TILE;

        #pragma unroll
        for (int kk = 0; kk < 4; kk++) {     // 4 x k32 steps per 128B chunk
            int cbyte = kk * 32 + lcol;
            uint32_t a[2][4];
            #pragma unroll
            for (int mi = 0; mi < 2; mi++) {
                int r = wm * 32 + mi * 16 + lrow;
                uint32_t off = (uint32_t)(r * ROWB + cbyte);
                LDMATRIX_X4(a[mi][0], a[mi][1], a[mi][2], a[mi][3],
                            sA + sw128(off));
            }
            uint32_t b[4][4];
            #pragma unroll
            for (int nj = 0; nj < 4; nj++) {
                int r = wn * 64 + nj * 16 + lrow;
                uint32_t off = (uint32_t)(r * ROWB + cbyte);
                LDMATRIX_X4(b[nj][0], b[nj][1], b[nj][2], b[nj][3],
                            sB + sw128(off));
            }
            // r0=(n0-7,k0-15)=b0lo, r1=(n8-15,k0-15)=b0hi,
            // r2=(n0-7,k16-31)=b1lo, r3=(n8-15,k16-31)=b1hi
            #pragma unroll
            for (int mi = 0; mi < 2; mi++) {
                #pragma unroll
                for (int j = 0; j < 8; j++) {
                    int nj = j >> 1, sel = j & 1;
                    MMA_FP8(acc[mi][j], a[mi], b[nj][sel], b[nj][sel + 2]);
                }
            }
        }
        __syncthreads();
    }

    // Dequant scale (matches reference op order)
    float xs = 448.0f / fmaxf(__uint_as_float(g_amax[0]), 1e-12f);
    float ws = 448.0f / fmaxf(__uint_as_float(g_amax[1]), 1e-12f);
    float inv = (1.0f / xs) * (1.0f / ws);

    int row0 = m_tile * BM + wm * 32 + (lane >> 2);
    int col0 = n_tile * BN + wn * 64 + (lane & 3) * 2;
    #pragma unroll
    for (int mi = 0; mi < 2; mi++) {
        #pragma unroll
        for (int j = 0; j < 8; j++) {
            float* p0 = out + (size_t)(row0 + mi * 16) * NDIM + col0 + j * 8;
            float* p1 = p0 + 8 * NDIM;
            float2 v0 = make_float2(acc[mi][j][0] * inv, acc[mi][j][1] * inv);
            float2 v1 = make_float2(acc[mi][j][2] * inv, acc[mi][j][3] * inv);
            *reinterpret_cast<float2*>(p0) = v0;
            *reinterpret_cast<float2*>(p1) = v1;
        }
    }
}

// ---------------------------------------------------------------------------
// Launch
// ---------------------------------------------------------------------------
extern "C" void kernel_launch(void* const* d_in, const int* in_sizes, int n_in,
                              void* d_out, int out_size) {
    const float* x = (const float*)d_in[0];
    const float* w = (const float*)d_in[1];
    if (n_in >= 2 && in_sizes[0] == KDIM * NDIM && in_sizes[1] != KDIM * NDIM) {
        const float* t = x; x = w; w = t;
    }
    float* out = (float*)d_out;

    init_amax_kernel<<<1, 32>>>();
    amax_kernel<<<2048, 256>>>((const float4*)x, (int)(MDIM * KDIM / 4), 0);
    amax_kernel<<<64, 256>>>((const float4*)w, KDIM * NDIM / 4, 1);
    quant_x_kernel<<<2048, 256>>>((const float4*)x, (int)(MDIM * KDIM / 4));
    quant_w_kernel<<<(KDIM * NDIM + 255) / 256, 256>>>(w);

    cudaFuncSetAttribute(gemm_kernel, cudaFuncAttributeMaxDynamicSharedMemorySize,
                         (int)SMEM_DYN);
    dim3 grid(NDIM / BN, (unsigned)(MDIM / BM));
    gemm_kernel<<<grid, 256, SMEM_DYN>>>(out);
}

// round 7
// speedup vs baseline: 1.1447x; 1.1447x over previous
#include <cuda_runtime.h>
#include <cuda_fp8.h>
#include <cuda_fp16.h>
#include <cstdint>

// ============================================================================
// out = dequant( fp8_quant(x) @ fp8_quant(weight^T)^T )
//   x: [8, 8192, 512] f32 -> M=65536, K=512; weight: [512,512] -> [N,K]
// Per-tensor dynamic scales: s = 448 / max(amax, 1e-12)
//
// Plain sm_103 target (no tcgen05). R6 showed fp8 mma.sync is SLOWER than
// fp16 HMMA here -> back to e4m3->fp16 exact widening + m16n8k16 HMMA,
// now with a 3-stage cp.async pipeline and streaming load/store hints.
// ============================================================================

static constexpr int KDIM = 512;
static constexpr int NDIM = 512;
static constexpr long long MDIM = 65536LL;

__device__ unsigned g_amax[2];                  // bits of amax(x), amax(w)
__device__ __half   g_xh[33554432];             // M*K quantized x as fp16
__device__ __half   g_wh[262144];               // N*K quantized weight^T as fp16

// ---------------------------------------------------------------------------
__device__ __forceinline__ uint32_t smem_u32(const void* p) {
    uint32_t a;
    asm("{ .reg .u64 t; cvta.to.shared.u64 t, %1; cvt.u32.u64 %0, t; }"
        : "=r"(a) : "l"(p));
    return a;
}

__device__ __forceinline__ float4 ldcs4(const float4* p) {
    float4 v;
    asm volatile("ld.global.cs.v4.f32 {%0,%1,%2,%3}, [%4];"
                 : "=f"(v.x), "=f"(v.y), "=f"(v.z), "=f"(v.w) : "l"(p));
    return v;
}

__device__ __forceinline__ void stcs2(float* p, float2 v) {
    asm volatile("st.global.cs.v2.f32 [%0], {%1,%2};" :: "l"(p), "f"(v.x), "f"(v.y));
}

#define CP_ASYNC16(dst, src) \
    asm volatile("cp.async.cg.shared.global [%0], [%1], 16;" :: "r"(dst), "l"(src))
#define CP_COMMIT() asm volatile("cp.async.commit_group;" ::: "memory")
#define CP_WAIT(n)  asm volatile("cp.async.wait_group %0;" :: "n"(n) : "memory")

#define LDMATRIX_X4(r0, r1, r2, r3, addr) \
    asm volatile("ldmatrix.sync.aligned.m8n8.x4.shared.b16 {%0,%1,%2,%3}, [%4];" \
                 : "=r"(r0), "=r"(r1), "=r"(r2), "=r"(r3) : "r"(addr))

#define MMA_16816(d, a, b0, b1) \
    asm volatile("mma.sync.aligned.m16n8k16.row.col.f32.f16.f16.f32 " \
                 "{%0,%1,%2,%3}, {%4,%5,%6,%7}, {%8,%9}, {%0,%1,%2,%3};" \
                 : "+f"((d)[0]), "+f"((d)[1]), "+f"((d)[2]), "+f"((d)[3]) \
                 : "r"((a)[0]), "r"((a)[1]), "r"((a)[2]), "r"((a)[3]), \
                   "r"(b0), "r"(b1))

__device__ __forceinline__ uint32_t sw128(uint32_t off) {
    return off ^ ((off >> 3) & 0x70);
}

// ---------------------------------------------------------------------------
// Kernel 0: zero amax accumulators
// ---------------------------------------------------------------------------
__global__ void init_amax_kernel() {
    if (threadIdx.x < 2) g_amax[threadIdx.x] = 0u;
}

// ---------------------------------------------------------------------------
// Kernel 1: global amax (float4 grid-stride, streaming loads)
// ---------------------------------------------------------------------------
__global__ void amax_kernel(const float4* __restrict__ p, int n4, int dst_idx) {
    float m = 0.0f;
    for (int i = blockIdx.x * blockDim.x + threadIdx.x; i < n4;
         i += gridDim.x * blockDim.x) {
        float4 v = ldcs4(p + i);
        m = fmaxf(m, fmaxf(fmaxf(fabsf(v.x), fabsf(v.y)),
                           fmaxf(fabsf(v.z), fabsf(v.w))));
    }
    #pragma unroll
    for (int o = 16; o > 0; o >>= 1) m = fmaxf(m, __shfl_xor_sync(0xFFFFFFFFu, m, o));
    __shared__ float sm[8];
    if ((threadIdx.x & 31) == 0) sm[threadIdx.x >> 5] = m;
    __syncthreads();
    if (threadIdx.x < 32) {
        float v = (threadIdx.x < (blockDim.x >> 5)) ? sm[threadIdx.x] : 0.0f;
        #pragma unroll
        for (int o = 4; o > 0; o >>= 1) v = fmaxf(v, __shfl_xor_sync(0xFFFFFFFFu, v, o));
        if (threadIdx.x == 0) atomicMax(&g_amax[dst_idx], __float_as_uint(v));
    }
}

// ---------------------------------------------------------------------------
// Kernel 2: quantize x: f32 -> e4m3 (RN satfinite, as reference) -> f16
// ---------------------------------------------------------------------------
__global__ void quant_x_kernel(const float4* __restrict__ x, int n4) {
    float scale = 448.0f / fmaxf(__uint_as_float(g_amax[0]), 1e-12f);
    uint2* __restrict__ out = reinterpret_cast<uint2*>(g_xh);
    for (int i = blockIdx.x * blockDim.x + threadIdx.x; i < n4;
         i += gridDim.x * blockDim.x) {
        float4 v = ldcs4(x + i);
        __half h0 = __half(__nv_cvt_fp8_to_halfraw(
            __nv_cvt_float_to_fp8(v.x * scale, __NV_SATFINITE, __NV_E4M3), __NV_E4M3));
        __half h1 = __half(__nv_cvt_fp8_to_halfraw(
            __nv_cvt_float_to_fp8(v.y * scale, __NV_SATFINITE, __NV_E4M3), __NV_E4M3));
        __half h2 = __half(__nv_cvt_fp8_to_halfraw(
            __nv_cvt_float_to_fp8(v.z * scale, __NV_SATFINITE, __NV_E4M3), __NV_E4M3));
        __half h3 = __half(__nv_cvt_fp8_to_halfraw(
            __nv_cvt_float_to_fp8(v.w * scale, __NV_SATFINITE, __NV_E4M3), __NV_E4M3));
        uint2 o;
        o.x = (uint32_t)__half_as_ushort(h0) | ((uint32_t)__half_as_ushort(h1) << 16);
        o.y = (uint32_t)__half_as_ushort(h2) | ((uint32_t)__half_as_ushort(h3) << 16);
        out[i] = o;
    }
}

// ---------------------------------------------------------------------------
// Kernel 3: quantize weight [K,N] -> g_wh [N,K] (transposed) as f16
// ---------------------------------------------------------------------------
__global__ void quant_w_kernel(const float* __restrict__ w) {
    int idx = blockIdx.x * blockDim.x + threadIdx.x;   // idx = k*512 + n
    if (idx >= KDIM * NDIM) return;
    float scale = 448.0f / fmaxf(__uint_as_float(g_amax[1]), 1e-12f);
    int k = idx >> 9;
    int n = idx & 511;
    g_wh[n * KDIM + k] = __half(__nv_cvt_fp8_to_halfraw(
        __nv_cvt_float_to_fp8(w[idx] * scale, __NV_SATFINITE, __NV_E4M3), __NV_E4M3));
}

// ---------------------------------------------------------------------------
// Kernel 4: fp16 HMMA GEMM, 3-stage cp.async pipeline
// CTA tile 128x128, BK=64 halfs (128 B SW128 rows), 8 warps 4x2, warp 32x64.
// ---------------------------------------------------------------------------
static constexpr int BM = 128;
static constexpr int BN = 128;
static constexpr int BK = 64;                      // halfs per chunk
static constexpr int ROWB = 128;                   // bytes per smem row
static constexpr int A_TILE = BM * ROWB;           // 16384 B
static constexpr int B_TILE = BN * ROWB;           // 16384 B
static constexpr int STAGE = A_TILE + B_TILE;      // 32768 B
static constexpr int NSTAGE = 3;
static constexpr uint32_t SMEM_DYN = NSTAGE * STAGE;   // 98304 B
static constexpr int NCHUNK = KDIM / BK;           // 8

__device__ __forceinline__ void load_tile(uint32_t smem_dst,
                                          const __half* __restrict__ gsrc,
                                          int k0, int tid) {
    #pragma unroll
    for (int i = 0; i < 4; i++) {
        int l = tid + i * 256;               // 0..1023 chunk id
        int r = l >> 3;                      // row
        int c = (l & 7) * 8;                 // half offset within chunk row
        uint32_t off = (uint32_t)(r * ROWB + c * 2);
        CP_ASYNC16(smem_dst + sw128(off), gsrc + (size_t)r * KDIM + k0 + c);
    }
}

__global__ void __launch_bounds__(256, 2) gemm_kernel(float* __restrict__ out) {
    extern __shared__ char smem[];
    uint32_t base = smem_u32(smem);
    int tid = threadIdx.x;
    int wid = tid >> 5;
    int lane = tid & 31;
    int wm = wid & 3;            // 4 warps along M (32 rows each)
    int wn = wid >> 2;           // 2 warps along N (64 cols each)
    int n_tile = blockIdx.x;     // 0..3
    int m_tile = blockIdx.y;     // 0..511

    const __half* gA = g_xh + (size_t)m_tile * BM * KDIM;
    const __half* gB = g_wh + (size_t)n_tile * BN * KDIM;

    float acc[2][8][4];
    #pragma unroll
    for (int mi = 0; mi < 2; mi++)
        #pragma unroll
        for (int j = 0; j < 8; j++)
            #pragma unroll
            for (int t = 0; t < 4; t++) acc[mi][j][t] = 0.0f;

    // Prologue: stages 0 and 1
    load_tile(base, gA, 0, tid);
    load_tile(base + A_TILE, gB, 0, tid);
    CP_COMMIT();
    load_tile(base + STAGE, gA, BK, tid);
    load_tile(base + STAGE + A_TILE, gB, BK, tid);
    CP_COMMIT();

    int lrow = lane & 15;
    int lcol8 = (lane >> 4) * 8;     // half offset

    int slot = 0;
    #pragma unroll 1
    for (int it = 0; it < NCHUNK; it++) {
        CP_WAIT(1);                  // stage `it` landed; one load may still fly
        __syncthreads();             // also releases slot overwritten below

        if (it + 2 < NCHUNK) {
            int ns = slot + 2;
            if (ns >= NSTAGE) ns -= NSTAGE;
            uint32_t nb = base + (uint32_t)ns * STAGE;
            load_tile(nb, gA, (it + 2) * BK, tid);
            load_tile(nb + A_TILE, gB, (it + 2) * BK, tid);
            CP_COMMIT();
        } else {
            CP_COMMIT();             // keep group count in step for CP_WAIT(1)
        }

        uint32_t sA = base + (uint32_t)slot * STAGE;
        uint32_t sB = sA + A_TILE;

        #pragma unroll
        for (int kk = 0; kk < 4; kk++) {
            int chalf = kk * 16 + lcol8;
            uint32_t a[2][4];
            #pragma unroll
            for (int mi = 0; mi < 2; mi++) {
                int r = wm * 32 + mi * 16 + lrow;
                uint32_t off = (uint32_t)(r * ROWB + chalf * 2);
                LDMATRIX_X4(a[mi][0], a[mi][1], a[mi][2], a[mi][3],
                            sA + sw128(off));
            }
            uint32_t b[4][4];
            #pragma unroll
            for (int nj = 0; nj < 4; nj++) {
                int r = wn * 64 + nj * 16 + lrow;
                uint32_t off = (uint32_t)(r * ROWB + chalf * 2);
                LDMATRIX_X4(b[nj][0], b[nj][1], b[nj][2], b[nj][3],
                            sB + sw128(off));
            }
            #pragma unroll
            for (int mi = 0; mi < 2; mi++) {
                #pragma unroll
                for (int j = 0; j < 8; j++) {
                    int nj = j >> 1, sel = j & 1;
                    MMA_16816(acc[mi][j], a[mi], b[nj][sel], b[nj][sel + 2]);
                }
            }
        }

        if (++slot >= NSTAGE) slot = 0;
    }

    // Dequant scale (matches reference op order)
    float xs = 448.0f / fmaxf(__uint_as_float(g_amax[0]), 1e-12f);
    float ws = 448.0f / fmaxf(__uint_as_float(g_amax[1]), 1e-12f);
    float inv = (1.0f / xs) * (1.0f / ws);

    int row0 = m_tile * BM + wm * 32 + (lane >> 2);
    int col0 = n_tile * BN + wn * 64 + (lane & 3) * 2;
    #pragma unroll
    for (int mi = 0; mi < 2; mi++) {
        #pragma unroll
        for (int j = 0; j < 8; j++) {
            float* p0 = out + (size_t)(row0 + mi * 16) * NDIM + col0 + j * 8;
            float* p1 = p0 + 8 * NDIM;
            stcs2(p0, make_float2(acc[mi][j][0] * inv, acc[mi][j][1] * inv));
            stcs2(p1, make_float2(acc[mi][j][2] * inv, acc[mi][j][3] * inv));
        }
    }
}

// ---------------------------------------------------------------------------
// Launch
// ---------------------------------------------------------------------------
extern "C" void kernel_launch(void* const* d_in, const int* in_sizes, int n_in,
                              void* d_out, int out_size) {
    const float* x = (const float*)d_in[0];
    const float* w = (const float*)d_in[1];
    if (n_in >= 2 && in_sizes[0] == KDIM * NDIM && in_sizes[1] != KDIM * NDIM) {
        const float* t = x; x = w; w = t;
    }
    float* out = (float*)d_out;

    init_amax_kernel<<<1, 32>>>();
    amax_kernel<<<2048, 256>>>((const float4*)x, (int)(MDIM * KDIM / 4), 0);
    amax_kernel<<<64, 256>>>((const float4*)w, KDIM * NDIM / 4, 1);
    quant_x_kernel<<<2048, 256>>>((const float4*)x, (int)(MDIM * KDIM / 4));
    quant_w_kernel<<<(KDIM * NDIM + 255) / 256, 256>>>(w);

    cudaFuncSetAttribute(gemm_kernel, cudaFuncAttributeMaxDynamicSharedMemorySize,
                         (int)SMEM_DYN);
    dim3 grid(NDIM / BN, (unsigned)(MDIM / BM));
    gemm_kernel<<<grid, 256, SMEM_DYN>>>(out);
}